// round 15
// baseline (speedup 1.0000x reference)
#include <cuda_runtime.h>
#include <cuda_bf16.h>
#include <cstdint>

#define P     96
#define NN    9216
#define THR   0.9f
#define MAXM  1024                 // fast-path capacity (observed M ~ 922, fixed seed)
#define NWRD  288                  // NN/32 ballot words
#define FULLM 0xffffffffu
#define GRID  64
#define BLK   256
#define NTHR  (GRID * BLK)
#define NWARP (NTHR / 32)
#define DSMEM 45056                // 44KB dynamic smem (phase A / producer staging)

// device-global scratch (no runtime allocation allowed)
__device__ __align__(128) int          g_bar_cnt;    // own L2 line
__device__ __align__(128) volatile int g_bar_flag;   // own L2 line
__device__ __align__(128) int          g_parity;     // persistent barrier sense
__device__ __align__(128) volatile int g_rowcnt[32]; // per-word ready counters
__device__ float    g_sc[NN];
__device__ float4   g_bx[NN];
__device__ __align__(16) uint32_t g_mask32[MAXM * 32];  // row stride 32 = 128B line

// sense-reversing grid barrier (all GRID blocks co-resident; GRID <= SM count)
__device__ __forceinline__ void gbar(int target)
{
    __syncthreads();
    if (threadIdx.x == 0) {
        __threadfence();
        if (atomicAdd(&g_bar_cnt, 1) == GRID - 1) {
            g_bar_cnt = 0;
            __threadfence();
            g_bar_flag = target;
        } else {
            while (g_bar_flag != target) { }
            __threadfence();
        }
    }
    __syncthreads();
}

__device__ __forceinline__ bool iou_gt(const float4 bi, const float ai, const float4 bj)
{
    const float ix1 = fmaxf(bi.x, bj.x);
    const float iy1 = fmaxf(bi.y, bj.y);
    const float ix2 = fminf(bi.z, bj.z);
    const float iy2 = fminf(bi.w, bj.w);
    const float iw = fmaxf(__fsub_rn(ix2, ix1), 0.0f);
    const float ih = fmaxf(__fsub_rn(iy2, iy1), 0.0f);
    const float inter = __fmul_rn(iw, ih);
    const float aj = __fmul_rn(__fsub_rn(bj.z, bj.x), __fsub_rn(bj.w, bj.y));
    const float uni = __fsub_rn(__fadd_rn(ai, aj), inter);
    return (uni > 0.0f) && (__fdiv_rn(inter, uni) > 0.5f);
}

// decode box for flat index gid (mirrors reference op order; no FMA contraction)
__device__ __forceinline__ float4 decode_box(const float* __restrict__ x, int gid)
{
    const float fi = (float)(gid / P);
    const float fj = (float)(gid % P);
    const float bx = __fadd_rn(__fmul_rn(x[1 * NN + gid], 16.0f), __fmul_rn(fi, 16.0f));
    const float by = __fadd_rn(__fmul_rn(x[2 * NN + gid], 16.0f), __fmul_rn(fj, 16.0f));
    const float bw = __fmul_rn(x[3 * NN + gid], 1536.0f);
    const float bh = __fmul_rn(x[4 * NN + gid], 1536.0f);
    return make_float4(rintf(bx), rintf(by),
                       rintf(__fadd_rn(bw, bx)), rintf(__fadd_rn(bh, by)));
}

extern __shared__ unsigned char dsm[];   // dynamic smem, aliased per phase

__global__ void __launch_bounds__(BLK) k_all(
    const float* __restrict__ x, float* __restrict__ out, int out_size)
{
    // phase A aliases
    float*  s_sc  = reinterpret_cast<float*>(dsm);              // all NN scores (36KB)
    float*  s_cs  = reinterpret_cast<float*>(dsm + 36864);      // compacted scores (4KB)
    int*    s_cid = reinterpret_cast<int*>(dsm + 40960);        // compacted ids (4KB)
    // producer-phase alias
    float4* s_bx  = reinterpret_cast<float4*>(dsm);             // M ranked boxes (16KB)

    __shared__ uint32_t s_wrd[NWRD];
    __shared__ int      s_pref[NWRD + 1];
    __shared__ uint32_t s_keepw[32];
    __shared__ uint32_t s_kb[NN / 32];     // slow-path kept bitmap

    const int tid  = threadIdx.x;
    const int gtid = blockIdx.x * BLK + tid;
    const int lane = tid & 31;
    const int widx = tid >> 5;
    const int gw   = blockIdx.x * (BLK / 32) + widx;   // global warp id

    const int target = g_parity ^ 1;       // barrier sense for THIS replay

    // ---- phase A: zero out; LOCAL compact (identical in every block); rank --
    for (int i = gtid; i < out_size; i += NTHR) out[i] = 0.0f;

    {   // stage all scores (vectorized)
        const float4* __restrict__ x4 = reinterpret_cast<const float4*>(x);
        float4* s4 = reinterpret_cast<float4*>(s_sc);
        for (int i = tid; i < NN / 4; i += BLK) s4[i] = x4[i];
    }
    __syncthreads();

    for (int w = widx; w < NWRD; w += BLK / 32) {
        const uint32_t b = __ballot_sync(FULLM, s_sc[(w << 5) + lane] > THR);
        if (lane == 0) s_wrd[w] = b;
    }
    __syncthreads();

    if (widx == 0) {     // exclusive prefix over word popcounts (warp 0)
        int run = 0;
        for (int c = 0; c < NWRD; c += 32) {
            const int pc = __popc(s_wrd[c + lane]);
            int sc = pc;
            #pragma unroll
            for (int o = 1; o < 32; o <<= 1) {
                const int n = __shfl_up_sync(FULLM, sc, o);
                if (lane >= o) sc += n;
            }
            s_pref[c + lane] = run + sc - pc;
            run += __shfl_sync(FULLM, sc, 31);
        }
        if (lane == 0) s_pref[NWRD] = run;
    }
    __syncthreads();
    const int M = s_pref[NWRD];

    if (M <= MAXM) {
        for (int w = widx; w < NWRD; w += BLK / 32) {
            const uint32_t b = s_wrd[w];
            const int gid = (w << 5) + lane;
            if ((b >> lane) & 1u) {
                const int pos = s_pref[w] + __popc(b & ((1u << lane) - 1u));
                s_cs[pos]  = s_sc[gid];
                s_cid[pos] = gid;
            }
        }
        __syncthreads();

        for (int t = gw; t < M; t += NWARP) {   // warp-per-entry stable rank
            const float s  = s_cs[t];
            const int   id = s_cid[t];
            int r = 0;
            #pragma unroll 4
            for (int j = lane; j < M; j += 32) {
                const float sj = s_cs[j];
                const int   ij = s_cid[j];
                r += (sj > s) || ((sj == s) && (ij < id));
            }
            r = __reduce_add_sync(FULLM, r);
            if (lane == 0) { g_sc[r] = s; g_bx[r] = decode_box(x, id); }
        }
    } else {
        for (int gid = gw; gid < NN; gid += NWARP) {   // fallback rank (raw)
            const float s = s_sc[gid];
            if (!(s > THR)) continue;
            int r = 0;
            for (int j = lane; j < NN; j += 32) {
                const float sj = s_sc[j];
                r += (sj > s) || ((sj == s) && (j < gid));
            }
            r = __reduce_add_sync(FULLM, r);
            if (lane == 0) { g_sc[r] = s; g_bx[r] = decode_box(x, gid); }
        }
    }
    gbar(target);     // the ONLY grid barrier

    const bool wk = (out_size >= 6 * NN);

    if (M > 0 && M <= MAXM) {
        const int W = (M + 31) >> 5;

        if (blockIdx.x != 0) {
            // ---------------- PRODUCERS: mask rows, low i first --------------
            for (int j = tid; j < M; j += BLK) s_bx[j] = g_bx[j];
            __syncthreads();
            const int pw  = gw - (BLK / 32);      // 0..503
            const int npw = NWARP - (BLK / 32);
            for (int i = pw; i < M; i += npw) {
                const float4 bi = s_bx[i];
                const float  ai = __fmul_rn(__fsub_rn(bi.z, bi.x), __fsub_rn(bi.w, bi.y));
                uint32_t myword = 0u;
                for (int w = 0; w < W; ++w) {
                    const int j = (w << 5) + lane;
                    bool pred = false;
                    if (j < M) pred = iou_gt(bi, ai, s_bx[j]);
                    const uint32_t word = __ballot_sync(FULLM, pred);
                    if (lane == w) myword = word;
                }
                g_mask32[i * 32 + lane] = (lane < W) ? myword : 0u;
                __threadfence();                              // release the row
                if (lane == 0) atomicAdd((int*)&g_rowcnt[i >> 5], 1);
            }
            return;
        }

        // ---------------- CONSUMER (block 0): pipelined greedy walk ----------
        if (tid < 32) {
            const uint32_t mybit = 1u << lane;
            const uint32_t above = ~((2u << lane) - 1u);
            uint32_t rem = 0u;
            uint32_t bufA[32], bufB[32];
            uint32_t dA = 0u, dB = 0u;

            auto READY = [&](int w) {
                const int need = min(32, M - (w << 5));
                while (g_rowcnt[w] < need) { }
                __threadfence();                              // acquire the rows
            };
            auto LOADA = [&](int w) {
                const int base = w << 5;
                #pragma unroll
                for (int b = 0; b < 32; ++b) bufA[b] = g_mask32[(base + b) * 32 + lane];
                dA = g_mask32[(base + lane) * 32 + w];
            };
            auto LOADB = [&](int w) {
                const int base = w << 5;
                #pragma unroll
                for (int b = 0; b < 32; ++b) bufB[b] = g_mask32[(base + b) * 32 + lane];
                dB = g_mask32[(base + lane) * 32 + w];
            };
            auto PROC = [&](uint32_t (&buf)[32], uint32_t dval, int w) {
                const int base = w << 5;
                const int nval = M - base;
                const uint32_t vmask = (nval >= 32) ? FULLM : ((1u << nval) - 1u);
                const uint32_t rem_w = __shfl_sync(FULLM, rem, w);
                const uint32_t cand  = (~rem_w) & vmask;
                const uint32_t d = dval & above;

                uint32_t kept = cand;                 // Jacobi fixpoint (unroll 2)
                for (;;) {
                    uint32_t sup = __reduce_or_sync(FULLM, (kept & mybit) ? d : 0u);
                    const uint32_t k1 = cand & ~sup;
                    sup = __reduce_or_sync(FULLM, (k1 & mybit) ? d : 0u);
                    const uint32_t k2 = cand & ~sup;
                    if (k2 == k1) { kept = k2; break; }
                    if (k2 == kept) break;
                    kept = k2;
                }
                if (lane == 0) s_keepw[w] = kept;

                uint32_t acc = 0u;
                #pragma unroll
                for (int b = 0; b < 32; ++b)
                    acc |= (kept & (1u << b)) ? buf[b] : 0u;
                rem |= acc;
            };

            READY(0); LOADA(0);
            for (int w = 0; w < W; w += 2) {
                if (w + 1 < W) { READY(w + 1); LOADB(w + 1); }
                PROC(bufA, dA, w);
                if (w + 2 < W) { READY(w + 2); LOADA(w + 2); }
                if (w + 1 < W) PROC(bufB, dB, w + 1);
            }
        }
        __syncthreads();

        for (int i = tid; i < M; i += BLK) {
            if ((s_keepw[i >> 5] >> (i & 31)) & 1u) {
                const float4 bi = g_bx[i];
                out[i * 5 + 0] = g_sc[i];
                out[i * 5 + 1] = bi.x;
                out[i * 5 + 2] = bi.y;
                out[i * 5 + 3] = __fsub_rn(bi.z, bi.x);
                out[i * 5 + 4] = __fsub_rn(bi.w, bi.y);
                if (wk) out[5 * NN + i] = 1.0f;
            }
        }
        __syncthreads();
        // reset counters (all producer adds provably complete) + flip sense
        if (tid < 32) *(int*)&g_rowcnt[tid] = 0;
        if (tid == 0) g_parity = target;
        return;
    }

    if (M == 0) {
        if (blockIdx.x == 0 && tid == 0) g_parity = target;
        return;
    }

    // ---- M > MAXM fallback: block 0 serial direct-IoU NMS (never expected) --
    if (blockIdx.x != 0) return;
    for (int t = tid; t < NN / 32; t += BLK) s_kb[t] = 0u;
    __syncthreads();
    if (tid == 0) {
        for (int i = 0; i < M; ++i) {
            const float4 bi = g_bx[i];
            const float  ai = __fmul_rn(__fsub_rn(bi.z, bi.x), __fsub_rn(bi.w, bi.y));
            bool sup = false;
            for (int j = 0; j < i && !sup; ++j)
                if ((s_kb[j >> 5] >> (j & 31)) & 1u)
                    sup = iou_gt(bi, ai, g_bx[j]);
            if (!sup) {
                s_kb[i >> 5] |= 1u << (i & 31);
                out[i * 5 + 0] = g_sc[i];
                out[i * 5 + 1] = bi.x;
                out[i * 5 + 2] = bi.y;
                out[i * 5 + 3] = __fsub_rn(bi.z, bi.x);
                out[i * 5 + 4] = __fsub_rn(bi.w, bi.y);
                if (wk) out[5 * NN + i] = 1.0f;
            }
        }
        g_parity = target;
    }
}

// ---------------------------------------------------------------------------
extern "C" void kernel_launch(void* const* d_in, const int* in_sizes, int n_in,
                              void* d_out, int out_size)
{
    const float* x = (const float*)d_in[0];
    float* out = (float*)d_out;
    cudaFuncSetAttribute(k_all, cudaFuncAttributeMaxDynamicSharedMemorySize, DSMEM);
    k_all<<<GRID, BLK, DSMEM>>>(x, out, out_size);
}

// round 16
// speedup vs baseline: 1.6727x; 1.6727x over previous
#include <cuda_runtime.h>
#include <cuda_bf16.h>
#include <cstdint>

#define P     96
#define NN    9216
#define THR   0.9f
#define MAXM  1024                 // fast-path capacity (observed M ~ 922)
#define FULLM 0xffffffffu
#define GRID  64
#define BLK   256
#define NTHR  (GRID * BLK)
#define DSMEM (MAXM * 32 * 4)      // 128KB dynamic smem: full mask for reduce

// device-global scratch (no runtime allocation allowed)
__device__ int      g_cnt;
__device__ __align__(128) int          g_bar_cnt;   // own L2 line
__device__ __align__(128) volatile int g_bar_flag;  // own L2 line
__device__ float    g_csc[NN];
__device__ int      g_cid[NN];
__device__ float4   g_cbx[NN];
__device__ float    g_sc[NN];
__device__ float4   g_bx[NN];
__device__ __align__(16) uint32_t g_mask32[MAXM * 32];  // row stride 32 = 128B line

// grid-wide barrier (all GRID blocks co-resident; GRID <= SM count)
__device__ __forceinline__ void gbar(int phase)
{
    __syncthreads();
    if (threadIdx.x == 0) {
        __threadfence();
        if (atomicAdd(&g_bar_cnt, 1) == GRID - 1) {
            g_bar_cnt = 0;
            __threadfence();
            g_bar_flag = phase;
        } else {
            while (g_bar_flag < phase) { }
            __threadfence();
        }
    }
    __syncthreads();
}

// IoU(bi,bj) > 0.5 test, division-free.
// All coords are rintf-integers => inter/areas/union are EXACT integers < 2^24
// in fp32; for integers, rn(inter/union) > 0.5  <=>  2*inter > union.
__device__ __forceinline__ bool iou_gt(const float4 bi, const float ai, const float4 bj)
{
    const float ix1 = fmaxf(bi.x, bj.x);
    const float iy1 = fmaxf(bi.y, bj.y);
    const float ix2 = fminf(bi.z, bj.z);
    const float iy2 = fminf(bi.w, bj.w);
    const float iw = fmaxf(__fsub_rn(ix2, ix1), 0.0f);
    const float ih = fmaxf(__fsub_rn(iy2, iy1), 0.0f);
    const float inter = __fmul_rn(iw, ih);
    const float aj = __fmul_rn(__fsub_rn(bj.z, bj.x), __fsub_rn(bj.w, bj.y));
    const float uni = __fsub_rn(__fadd_rn(ai, aj), inter);
    return (uni > 0.0f) && (__fmul_rn(inter, 2.0f) > uni);
}

extern __shared__ uint32_t smask[];   // dynamic: staged mask (reduce phase)

__global__ void __launch_bounds__(BLK) k_all(
    const float* __restrict__ x, float* __restrict__ out, int out_size)
{
    __shared__ float    ss[MAXM];          // scores (rank phase)
    __shared__ int      sid[MAXM];         // ids    (rank phase)
    __shared__ float4   sbx[MAXM];         // boxes  (mask phase)
    __shared__ uint32_t sdiag[32 * 32];    // diagonal blocks (reduce)
    __shared__ uint32_t s_keepw[32];
    __shared__ uint32_t s_kb[NN / 32];     // slow-path kept bitmap

    const int tid  = threadIdx.x;
    const int gtid = blockIdx.x * BLK + tid;
    const int lane = tid & 31;
    const int widx = tid >> 5;             // warp within block (0..7)

    // ---------------- phase 0: zero output, compact valid boxes -------------
    for (int i = gtid; i < out_size; i += NTHR) out[i] = 0.0f;

    if (gtid < NN) {
        const float s = x[gtid];
        const bool valid = s > THR;
        const unsigned bal = __ballot_sync(FULLM, valid);
        if (valid) {
            const int leader = __ffs(bal) - 1;
            int base = 0;
            if (lane == leader) base = atomicAdd(&g_cnt, __popc(bal));
            base = __shfl_sync(bal, base, leader);
            const int pos = base + __popc(bal & ((1u << lane) - 1u));

            const float fi = (float)(gtid / P);
            const float fj = (float)(gtid % P);
            const float bx = __fadd_rn(__fmul_rn(x[1 * NN + gtid], 16.0f), __fmul_rn(fi, 16.0f));
            const float by = __fadd_rn(__fmul_rn(x[2 * NN + gtid], 16.0f), __fmul_rn(fj, 16.0f));
            const float bw = __fmul_rn(x[3 * NN + gtid], 1536.0f);
            const float bh = __fmul_rn(x[4 * NN + gtid], 1536.0f);

            g_csc[pos] = s;
            g_cid[pos] = gtid;
            g_cbx[pos] = make_float4(rintf(bx), rintf(by),
                                     rintf(__fadd_rn(bw, bx)), rintf(__fadd_rn(bh, by)));
        }
    }
    gbar(1);

    // ------- phase 1: warp-per-entry rank (stable) + immediate scatter ------
    const int M = g_cnt;
    if (M > 0 && M <= MAXM) {
        for (int j = tid; j < M; j += BLK) { ss[j] = g_csc[j]; sid[j] = g_cid[j]; }
        __syncthreads();
        for (int t = blockIdx.x * (BLK / 32) + widx; t < M; t += GRID * (BLK / 32)) {
            const float s  = ss[t];
            const int   id = sid[t];
            int r = 0;
            #pragma unroll 4
            for (int j = lane; j < M; j += 32) {
                const float sj = ss[j];
                const int   ij = sid[j];
                r += (sj > s) || ((sj == s) && (ij < id));
            }
            r = __reduce_add_sync(FULLM, r);
            if (lane == 0) { g_sc[r] = s; g_bx[r] = g_cbx[t]; }
        }
    } else if (M > MAXM) {
        for (int t = gtid; t < M; t += NTHR) {
            const float s  = g_csc[t];
            const int   id = g_cid[t];
            int r = 0;
            for (int j = 0; j < M; ++j) {
                const float sj = g_csc[j];
                const int   ij = g_cid[j];
                r += (sj > s) || ((sj == s) && (ij < id));
            }
            g_sc[r] = s;
            g_bx[r] = g_cbx[t];
        }
    }
    gbar(2);

    // ---------------- phase 2: suppression mask (smem boxes, ballot) --------
    if (M > 0 && M <= MAXM) {
        const int W = (M + 31) >> 5;
        for (int j = tid; j < M; j += BLK) sbx[j] = g_bx[j];
        __syncthreads();
        for (int i = blockIdx.x * (BLK / 32) + widx; i < M; i += GRID * (BLK / 32)) {
            const float4 bi = sbx[i];
            const float  ai = __fmul_rn(__fsub_rn(bi.z, bi.x), __fsub_rn(bi.w, bi.y));
            uint32_t myword = 0u;
            for (int w = 0; w < W; ++w) {
                const int j = (w << 5) + lane;
                bool pred = false;
                if (j < M) pred = iou_gt(bi, ai, sbx[j]);
                const uint32_t word = __ballot_sync(FULLM, pred);
                if (lane == w) myword = word;
            }
            g_mask32[i * 32 + lane] = (lane < W) ? myword : 0u;  // full 128B line
        }
    }
    gbar(3);

    // ---------------- phase 3: greedy reduce (block 0 only) -----------------
    if (blockIdx.x != 0) return;
    const bool wk = (out_size >= 6 * NN);

    if (M > 0 && M <= MAXM) {
        const int W = (M + 31) >> 5;
        const int words = M * 32;

        // all 8 warps stage the full mask into dynamic smem (uint4 vectorized)
        {
            const uint4* __restrict__ src4 = reinterpret_cast<const uint4*>(g_mask32);
            uint4* dst4 = reinterpret_cast<uint4*>(smask);
            for (int t = tid; t < (words >> 2); t += BLK) dst4[t] = src4[t];
        }
        // diagonal blocks (transposed, conflict-free for the walk)
        for (int idx = tid; idx < (W << 5); idx += BLK)
            sdiag[idx] = (idx < M) ? g_mask32[idx * 32 + (idx >> 5)] : 0u;
        __syncthreads();

        if (tid < 32) {
            const uint32_t mybit = 1u << lane;
            const uint32_t above = ~((2u << lane) - 1u);   // bits strictly > lane
            uint32_t rem = 0u;

            for (int w = 0; w < W; ++w) {
                const int base = w << 5;

                // row data for this word: conflict-free LDS, fully pipelined
                uint32_t buf[32];
                #pragma unroll
                for (int b = 0; b < 32; ++b)
                    buf[b] = smask[(base + b) * 32 + lane];

                const int nval = M - base;
                const uint32_t vmask = (nval >= 32) ? FULLM : ((1u << nval) - 1u);
                const uint32_t rem_w = __shfl_sync(FULLM, rem, w);
                const uint32_t cand  = (~rem_w) & vmask;
                const uint32_t d = sdiag[base + lane] & above;

                // Jacobi fixpoint (unroll 2 per convergence check).
                // Prefix-stabilization: bits 0..t-1 exact after t iters; the
                // only stationary point is the unique greedy fixpoint.
                uint32_t kept = cand;
                for (;;) {
                    uint32_t sup = __reduce_or_sync(FULLM, (kept & mybit) ? d : 0u);
                    const uint32_t k1 = cand & ~sup;
                    sup = __reduce_or_sync(FULLM, (k1 & mybit) ? d : 0u);
                    const uint32_t k2 = cand & ~sup;
                    if (k2 == k1) { kept = k2; break; }
                    if (k2 == kept) break;      // safety (cannot 2-cycle, see above)
                    kept = k2;
                }
                if (lane == 0) s_keepw[w] = kept;

                // branch-free OR of kept rows into removed state
                uint32_t acc = 0u;
                #pragma unroll
                for (int b = 0; b < 32; ++b)
                    acc |= (kept & (1u << b)) ? buf[b] : 0u;
                rem |= acc;
            }
        }
        __syncthreads();

        for (int i = tid; i < M; i += BLK) {
            if ((s_keepw[i >> 5] >> (i & 31)) & 1u) {
                const float4 bi = g_bx[i];
                out[i * 5 + 0] = g_sc[i];
                out[i * 5 + 1] = bi.x;
                out[i * 5 + 2] = bi.y;
                out[i * 5 + 3] = __fsub_rn(bi.z, bi.x);
                out[i * 5 + 4] = __fsub_rn(bi.w, bi.y);
                if (wk) out[5 * NN + i] = 1.0f;
            }
        }
    } else if (M > MAXM) {
        // correct-but-slow fallback (never expected: seed-fixed M ~ 922)
        for (int t = tid; t < NN / 32; t += BLK) s_kb[t] = 0u;
        __syncthreads();
        if (tid == 0) {
            for (int i = 0; i < M; ++i) {
                const float4 bi = g_bx[i];
                const float  ai = __fmul_rn(__fsub_rn(bi.z, bi.x), __fsub_rn(bi.w, bi.y));
                bool sup = false;
                for (int j = 0; j < i && !sup; ++j)
                    if ((s_kb[j >> 5] >> (j & 31)) & 1u)
                        sup = iou_gt(bi, ai, g_bx[j]);
                if (!sup) {
                    s_kb[i >> 5] |= 1u << (i & 31);
                    out[i * 5 + 0] = g_sc[i];
                    out[i * 5 + 1] = bi.x;
                    out[i * 5 + 2] = bi.y;
                    out[i * 5 + 3] = __fsub_rn(bi.z, bi.x);
                    out[i * 5 + 4] = __fsub_rn(bi.w, bi.y);
                    if (wk) out[5 * NN + i] = 1.0f;
                }
            }
        }
        __syncthreads();
    }

    // deterministic state for the next graph replay
    if (tid == 0) { g_cnt = 0; g_bar_flag = 0; }
}

// ---------------------------------------------------------------------------
extern "C" void kernel_launch(void* const* d_in, const int* in_sizes, int n_in,
                              void* d_out, int out_size)
{
    const float* x = (const float*)d_in[0];
    float* out = (float*)d_out;
    cudaFuncSetAttribute(k_all, cudaFuncAttributeMaxDynamicSharedMemorySize, DSMEM);
    k_all<<<GRID, BLK, DSMEM>>>(x, out, out_size);
}

// round 17
// speedup vs baseline: 1.7530x; 1.0480x over previous
#include <cuda_runtime.h>
#include <cuda_bf16.h>
#include <cstdint>

#define P     96
#define NN    9216
#define THR   0.9f
#define MAXM  1024                 // fast-path capacity (observed M ~ 922)
#define FULLM 0xffffffffu
#define GRID  64
#define BLK   256
#define NTHR  (GRID * BLK)
#define NWARP (NTHR / 32)          // 512
#define DSMEM (MAXM * 32 * 4)      // 128KB dynamic smem: full mask for reduce

// device-global scratch (no runtime allocation allowed)
__device__ int      g_cnt;
__device__ __align__(128) int          g_bar_cnt;   // own L2 line
__device__ __align__(128) volatile int g_bar_flag;  // own L2 line
__device__ float    g_csc[NN];
__device__ int      g_cid[NN];
__device__ float4   g_cbx[NN];
__device__ float    g_sc[NN];
__device__ float4   g_bx[NN];
__device__ __align__(16) uint32_t g_mask32[MAXM * 32];  // row stride 32 = 128B line

// grid-wide barrier (all GRID blocks co-resident; GRID <= SM count)
__device__ __forceinline__ void gbar(int phase)
{
    __syncthreads();
    if (threadIdx.x == 0) {
        __threadfence();
        if (atomicAdd(&g_bar_cnt, 1) == GRID - 1) {
            g_bar_cnt = 0;
            __threadfence();
            g_bar_flag = phase;
        } else {
            while (g_bar_flag < phase) { }
            __threadfence();
        }
    }
    __syncthreads();
}

// IoU(bi,bj) > 0.5 test, division-free.
// All coords are rintf-integers => inter/areas/union are EXACT integers < 2^24
// in fp32; for integers, rn(inter/union) > 0.5  <=>  2*inter > union.
__device__ __forceinline__ bool iou_gt(const float4 bi, const float ai, const float4 bj)
{
    const float ix1 = fmaxf(bi.x, bj.x);
    const float iy1 = fmaxf(bi.y, bj.y);
    const float ix2 = fminf(bi.z, bj.z);
    const float iy2 = fminf(bi.w, bj.w);
    const float iw = fmaxf(__fsub_rn(ix2, ix1), 0.0f);
    const float ih = fmaxf(__fsub_rn(iy2, iy1), 0.0f);
    const float inter = __fmul_rn(iw, ih);
    const float aj = __fmul_rn(__fsub_rn(bj.z, bj.x), __fsub_rn(bj.w, bj.y));
    const float uni = __fsub_rn(__fadd_rn(ai, aj), inter);
    return (uni > 0.0f) && (__fmul_rn(inter, 2.0f) > uni);
}

extern __shared__ uint32_t smask[];   // dynamic: staged mask (reduce phase)

__global__ void __launch_bounds__(BLK) k_all(
    const float* __restrict__ x, float* __restrict__ out, int out_size)
{
    __shared__ float    ss[MAXM];          // scores (rank phase)
    __shared__ int      sid[MAXM];         // ids    (rank phase)
    __shared__ float4   sbx[MAXM];         // boxes  (mask phase)
    __shared__ uint32_t sdiag[32 * 32];    // diagonal blocks (reduce)
    __shared__ uint32_t s_keepw[32];
    __shared__ uint32_t s_kb[NN / 32];     // slow-path kept bitmap

    const int tid  = threadIdx.x;
    const int gtid = blockIdx.x * BLK + tid;
    const int lane = tid & 31;
    const int widx = tid >> 5;             // warp within block (0..7)
    const int gw   = blockIdx.x * (BLK / 32) + widx;   // global warp id (0..511)

    // ---------------- phase 0: zero output, compact valid boxes -------------
    for (int i = gtid; i < out_size; i += NTHR) out[i] = 0.0f;

    if (gtid < NN) {
        const float s = x[gtid];
        const bool valid = s > THR;
        const unsigned bal = __ballot_sync(FULLM, valid);
        if (valid) {
            const int leader = __ffs(bal) - 1;
            int base = 0;
            if (lane == leader) base = atomicAdd(&g_cnt, __popc(bal));
            base = __shfl_sync(bal, base, leader);
            const int pos = base + __popc(bal & ((1u << lane) - 1u));

            const float fi = (float)(gtid / P);
            const float fj = (float)(gtid % P);
            const float bx = __fadd_rn(__fmul_rn(x[1 * NN + gtid], 16.0f), __fmul_rn(fi, 16.0f));
            const float by = __fadd_rn(__fmul_rn(x[2 * NN + gtid], 16.0f), __fmul_rn(fj, 16.0f));
            const float bw = __fmul_rn(x[3 * NN + gtid], 1536.0f);
            const float bh = __fmul_rn(x[4 * NN + gtid], 1536.0f);

            g_csc[pos] = s;
            g_cid[pos] = gtid;
            g_cbx[pos] = make_float4(rintf(bx), rintf(by),
                                     rintf(__fadd_rn(bw, bx)), rintf(__fadd_rn(bh, by)));
        }
    }
    gbar(1);

    // ------- phase 1: warp-per-entry rank (stable) + immediate scatter ------
    const int M = g_cnt;
    if (M > 0 && M <= MAXM) {
        for (int j = tid; j < M; j += BLK) { ss[j] = g_csc[j]; sid[j] = g_cid[j]; }
        __syncthreads();
        for (int t = gw; t < M; t += NWARP) {
            const float s  = ss[t];
            const int   id = sid[t];
            int r = 0;
            #pragma unroll 4
            for (int j = lane; j < M; j += 32) {
                const float sj = ss[j];
                const int   ij = sid[j];
                r += (sj > s) || ((sj == s) && (ij < id));
            }
            r = __reduce_add_sync(FULLM, r);
            if (lane == 0) { g_sc[r] = s; g_bx[r] = g_cbx[t]; }
        }
    } else if (M > MAXM) {
        for (int t = gtid; t < M; t += NTHR) {
            const float s  = g_csc[t];
            const int   id = g_cid[t];
            int r = 0;
            for (int j = 0; j < M; ++j) {
                const float sj = g_csc[j];
                const int   ij = g_cid[j];
                r += (sj > s) || ((sj == s) && (ij < id));
            }
            g_sc[r] = s;
            g_bx[r] = g_cbx[t];
        }
    }
    gbar(2);

    // --- phase 2: suppression mask, UPPER TRIANGLE only, mirror-balanced ----
    // The greedy walk never consults bits j < i of row i (diag is masked with
    // `above`; lower-word contributions land on already-processed rem words),
    // so row i only needs words w >= i>>5. Lower words are written as zeros.
    // Row assignment {gw, 1023-gw} gives每 warp a near-constant word budget.
    if (M > 0 && M <= MAXM) {
        const int W = (M + 31) >> 5;
        for (int j = tid; j < M; j += BLK) sbx[j] = g_bx[j];
        __syncthreads();
        #pragma unroll
        for (int half = 0; half < 2; ++half) {
            const int i = half ? (2 * NWARP - 1 - gw) : gw;
            if (i >= M) continue;
            const float4 bi = sbx[i];
            const float  ai = __fmul_rn(__fsub_rn(bi.z, bi.x), __fsub_rn(bi.w, bi.y));
            const int w0 = i >> 5;
            uint32_t myword = 0u;
            for (int w = w0; w < W; ++w) {
                const int j = (w << 5) + lane;
                bool pred = false;
                if (j < M) pred = iou_gt(bi, ai, sbx[j]);
                const uint32_t word = __ballot_sync(FULLM, pred);
                if (lane == w) myword = word;
            }
            g_mask32[i * 32 + lane] = (lane < W) ? myword : 0u;  // zeros below w0
        }
    }
    gbar(3);

    // ---------------- phase 3: greedy reduce (block 0 only) -----------------
    if (blockIdx.x != 0) return;
    const bool wk = (out_size >= 6 * NN);

    if (M > 0 && M <= MAXM) {
        const int W = (M + 31) >> 5;
        const int words = M * 32;

        // all 8 warps stage the full mask into dynamic smem (uint4 vectorized)
        {
            const uint4* __restrict__ src4 = reinterpret_cast<const uint4*>(g_mask32);
            uint4* dst4 = reinterpret_cast<uint4*>(smask);
            for (int t = tid; t < (words >> 2); t += BLK) dst4[t] = src4[t];
        }
        // diagonal blocks (transposed, conflict-free for the walk)
        for (int idx = tid; idx < (W << 5); idx += BLK)
            sdiag[idx] = (idx < M) ? g_mask32[idx * 32 + (idx >> 5)] : 0u;
        __syncthreads();

        if (tid < 32) {
            const uint32_t mybit = 1u << lane;
            const uint32_t above = ~((2u << lane) - 1u);   // bits strictly > lane
            uint32_t rem = 0u;

            for (int w = 0; w < W; ++w) {
                const int base = w << 5;

                // row data for this word: conflict-free LDS, fully pipelined
                uint32_t buf[32];
                #pragma unroll
                for (int b = 0; b < 32; ++b)
                    buf[b] = smask[(base + b) * 32 + lane];

                const int nval = M - base;
                const uint32_t vmask = (nval >= 32) ? FULLM : ((1u << nval) - 1u);
                const uint32_t rem_w = __shfl_sync(FULLM, rem, w);
                const uint32_t cand  = (~rem_w) & vmask;
                const uint32_t d = sdiag[base + lane] & above;

                // Jacobi fixpoint (unroll 2 per convergence check).
                uint32_t kept = cand;
                for (;;) {
                    uint32_t sup = __reduce_or_sync(FULLM, (kept & mybit) ? d : 0u);
                    const uint32_t k1 = cand & ~sup;
                    sup = __reduce_or_sync(FULLM, (k1 & mybit) ? d : 0u);
                    const uint32_t k2 = cand & ~sup;
                    if (k2 == k1) { kept = k2; break; }
                    if (k2 == kept) break;
                    kept = k2;
                }
                if (lane == 0) s_keepw[w] = kept;

                // branch-free OR of kept rows into removed state
                uint32_t acc = 0u;
                #pragma unroll
                for (int b = 0; b < 32; ++b)
                    acc |= (kept & (1u << b)) ? buf[b] : 0u;
                rem |= acc;
            }
        }
        __syncthreads();

        for (int i = tid; i < M; i += BLK) {
            if ((s_keepw[i >> 5] >> (i & 31)) & 1u) {
                const float4 bi = g_bx[i];
                out[i * 5 + 0] = g_sc[i];
                out[i * 5 + 1] = bi.x;
                out[i * 5 + 2] = bi.y;
                out[i * 5 + 3] = __fsub_rn(bi.z, bi.x);
                out[i * 5 + 4] = __fsub_rn(bi.w, bi.y);
                if (wk) out[5 * NN + i] = 1.0f;
            }
        }
    } else if (M > MAXM) {
        // correct-but-slow fallback (never expected: seed-fixed M ~ 922)
        for (int t = tid; t < NN / 32; t += BLK) s_kb[t] = 0u;
        __syncthreads();
        if (tid == 0) {
            for (int i = 0; i < M; ++i) {
                const float4 bi = g_bx[i];
                const float  ai = __fmul_rn(__fsub_rn(bi.z, bi.x), __fsub_rn(bi.w, bi.y));
                bool sup = false;
                for (int j = 0; j < i && !sup; ++j)
                    if ((s_kb[j >> 5] >> (j & 31)) & 1u)
                        sup = iou_gt(bi, ai, g_bx[j]);
                if (!sup) {
                    s_kb[i >> 5] |= 1u << (i & 31);
                    out[i * 5 + 0] = g_sc[i];
                    out[i * 5 + 1] = bi.x;
                    out[i * 5 + 2] = bi.y;
                    out[i * 5 + 3] = __fsub_rn(bi.z, bi.x);
                    out[i * 5 + 4] = __fsub_rn(bi.w, bi.y);
                    if (wk) out[5 * NN + i] = 1.0f;
                }
            }
        }
        __syncthreads();
    }

    // deterministic state for the next graph replay
    if (tid == 0) { g_cnt = 0; g_bar_flag = 0; }
}

// ---------------------------------------------------------------------------
extern "C" void kernel_launch(void* const* d_in, const int* in_sizes, int n_in,
                              void* d_out, int out_size)
{
    const float* x = (const float*)d_in[0];
    float* out = (float*)d_out;
    cudaFuncSetAttribute(k_all, cudaFuncAttributeMaxDynamicSharedMemorySize, DSMEM);
    k_all<<<GRID, BLK, DSMEM>>>(x, out, out_size);
}